// round 1
// baseline (speedup 1.0000x reference)
#include <cuda_runtime.h>
#include <math.h>

#define T 32768
#define D 1024
#define L 128                 // steps per chunk
#define NCHUNK (T / L)        // 256

__device__ __constant__ float c_dummy; // (nothing needed; constants inline)

static __device__ float g_sum  [NCHUNK * D];
static __device__ float g_sumsq[NCHUNK * D];
static __device__ float g_smu  [NCHUNK * D];
static __device__ float g_A    [NCHUNK * D];
static __device__ float g_B    [NCHUNK * D];
static __device__ float g_muin [NCHUNK * D];
static __device__ float g_varin[NCHUNK * D];

#define ETA_MU  0.01f
#define ETA_VAR 0.02f

// Pass B: one read of x. Per (chunk, col): column-partial sum/sumsq for global
// stats, plus the chunk-local linear-scan aggregates:
//   S_mu = local mu scan with zero carry-in
//   A    = sum_i 0.98^{L-1-i} * 0.02 * e_i^2         (e_i = x_i - mu_i^{(0)})
//   B    = sum_i 0.98^{L-1-i} * 0.02 * 2 e_i p_i     (p_i = 0.99^{i+1})
// so that S_var(mu_in) = A - B*mu_in + Cc*mu_in^2  (Cc is a pure constant).
__global__ void __launch_bounds__(128) pass_b(const float* __restrict__ x) {
    const int col = blockIdx.x * 128 + threadIdx.x;
    const int c   = blockIdx.y;
    const float* xp = x + (size_t)c * L * D + col;

    float sum = 0.f, sumsq = 0.f;
    float s = 0.f, p = 1.f, A = 0.f, Bc = 0.f;

    #pragma unroll 4
    for (int i = 0; i < L; i++) {
        float xv = xp[(size_t)i * D];
        sum += xv;
        sumsq = fmaf(xv, xv, sumsq);
        s = fmaf(ETA_MU, xv - s, s);          // local mu scan (zero init)
        p *= (1.0f - ETA_MU);                 // p_i = 0.99^{i+1}
        float e = xv - s;
        A  = fmaf(1.0f - ETA_VAR, A,  ETA_VAR * e * e);
        Bc = fmaf(1.0f - ETA_VAR, Bc, (2.0f * ETA_VAR) * e * p);
    }
    const int idx = c * D + col;
    g_sum[idx]   = sum;
    g_sumsq[idx] = sumsq;
    g_smu[idx]   = s;
    g_A[idx]     = A;
    g_B[idx]     = Bc;
}

// Pass C: per column — global stats (mu0, unbiased std0: the reference stores
// std into the 'var' slot!), then the chunk-granularity carry recurrence for
// mu_in / var_in of every chunk. 1024 threads total; trivial runtime.
__global__ void __launch_bounds__(128) pass_c() {
    const int col = blockIdx.x * 128 + threadIdx.x;

    float sum = 0.f, sumsq = 0.f;
    for (int c = 0; c < NCHUNK; c++) {
        sum   += g_sum  [c * D + col];
        sumsq += g_sumsq[c * D + col];
    }
    const float mu0  = sum / (float)T;
    const float var0 = (sumsq - sum * mu0) / (float)(T - 1);
    const float std0 = sqrtf(fmaxf(var0, 0.0f));   // torch.std(ddof=1) quirk

    // Cc = sum_i 0.98^{L-1-i} * 0.02 * p_i^2  (data-independent constant)
    float pv = 1.f, Cc = 0.f;
    const float q = (1.0f - ETA_MU) * (1.0f - ETA_MU);
    #pragma unroll
    for (int i = 0; i < L; i++) {
        pv *= q;
        Cc = fmaf(1.0f - ETA_VAR, Cc, ETA_VAR * pv);
    }

    // high-precision chunk decay factors
    const float dL  = (float)pow((double)(1.0f - ETA_MU),  (double)L);
    const float dvL = (float)pow((double)(1.0f - ETA_VAR), (double)L);

    float m = mu0, v = std0;
    for (int c = 0; c < NCHUNK; c++) {
        const int idx = c * D + col;
        g_muin[idx]  = m;
        g_varin[idx] = v;
        float Sv = fmaf(Cc * m, m, fmaf(-g_B[idx], m, g_A[idx]));
        v = fmaf(dvL, v, Sv);
        m = fmaf(dL,  m, g_smu[idx]);
    }
}

// Pass F: replay each chunk with correct carries; write norm, mu, var.
// Output layout: d_out[0 .. T*D)          = norm_x  [T, D]
//                d_out[T*D .. T*D + T*2D) = additional_info [T, 2D] = [mu | var]
__global__ void __launch_bounds__(128) pass_f(const float* __restrict__ x,
                                              float* __restrict__ out) {
    const int col = blockIdx.x * 128 + threadIdx.x;
    const int c   = blockIdx.y;
    const int idx = c * D + col;

    float mu  = g_muin[idx];
    float var = g_varin[idx];

    const int t0 = c * L;
    const float* __restrict__ xp  = x   + (size_t)t0 * D + col;
    float* __restrict__ nrm       = out + (size_t)t0 * D + col;
    float* __restrict__ info      = out + (size_t)T * D + (size_t)t0 * (2 * D) + col;

    #pragma unroll 4
    for (int i = 0; i < L; i++) {
        float xv = xp[(size_t)i * D];
        mu = fmaf(ETA_MU, xv - mu, mu);
        float d2 = xv - mu;
        var = fmaf(1.0f - ETA_VAR, var, ETA_VAR * d2 * d2);
        nrm [(size_t)i * D]             = d2 * rsqrtf(var);
        info[(size_t)i * (2 * D)]       = mu;
        info[(size_t)i * (2 * D) + D]   = var;
    }
}

extern "C" void kernel_launch(void* const* d_in, const int* in_sizes, int n_in,
                              void* d_out, int out_size) {
    const float* x = (const float*)d_in[0];
    float* out = (float*)d_out;
    (void)in_sizes; (void)n_in; (void)out_size;

    dim3 blk(128);
    dim3 grid(D / 128, NCHUNK);
    pass_b<<<grid, blk>>>(x);
    pass_c<<<D / 128, blk>>>();
    pass_f<<<grid, blk>>>(x, out);
}